// round 15
// baseline (speedup 1.0000x reference)
#include <cuda_runtime.h>
#include <cuda_bf16.h>

// Problem constants (fixed by the reference)
#define NNODES 50000
#define NEDGES 800000
#define D      64
#define NCLS   16

// Persistent scatter grid: 148 SMs x 8 blocks (grid-stride -> any SM count OK)
#define SCBLOCKS 1184

// Scratch (device globals)
__device__ float4 g_t1[NNODES * NCLS / 4];   // M1 x
__device__ float4 g_t2[NNODES * NCLS / 4];   // u2 + v1, then += A t1
__device__ float4 g_M4[3 * NCLS * D / 4];    // M1, M2, M3
__device__ float  g_v[2 * NCLS];             // v1, c
__device__ int    g_is64;                    // 1 if edge_index is int64
__device__ int2   g_edge2[NEDGES];           // packed (src, dst)

// ---------------------------------------------------------------------------
// Fused: dtype detect + unified weight fold. ONE block, 1024 threads.
// ---------------------------------------------------------------------------
__global__ __launch_bounds__(1024) void dwfold_kernel(
        const unsigned int* __restrict__ widx,
        const float* __restrict__ W1r, const float* __restrict__ b1,
        const float* __restrict__ W1o, const float* __restrict__ W2r,
        const float* __restrict__ b2,  const float* __restrict__ W2o,
        const float* __restrict__ Wl,  const float* __restrict__ bl) {
    __shared__ float sWa[D * D];        // W2r then W1r
    __shared__ float sWb[D * D];        // W2o then W1o
    __shared__ float sWl[NCLS * D];
    __shared__ float sPr[NCLS * D];
    __shared__ float sPo[NCLS * D];
    __shared__ float sb1[D], sb2[D], sur[D], suo[D];
    __shared__ int any_nonzero;
    const int tid = threadIdx.x;

    // ---- dtype detect ----
    if (tid == 0) any_nonzero = 0;
    __syncthreads();
    {
        unsigned int acc = 0;
        for (int i = tid; i < 4096; i += 1024) acc |= widx[2 * i + 1];
        if (acc) any_nonzero = 1;
    }

    // ---- Phase 1 loads ----
    {
        const int nf4 = D * D / 4;                      // 1024
        for (int i = tid; i < nf4; i += 1024) {
            ((float4*)sWa)[i] = ((const float4*)W2r)[i];
            ((float4*)sWb)[i] = ((const float4*)W2o)[i];
        }
        if (tid < NCLS * D / 4)
            ((float4*)sWl)[tid] = ((const float4*)Wl)[tid];
        if (tid < D / 4) {
            ((float4*)sb1)[tid] = ((const float4*)b1)[tid];
            ((float4*)sb2)[tid] = ((const float4*)b2)[tid];
        }
    }
    __syncthreads();
    if (tid == 0) g_is64 = any_nonzero ? 0 : 1;

    if (tid < D) {
        float s = 0.f;
        for (int k = 0; k < D; k++) s += sWa[tid * D + k] * sb1[k];
        sur[tid] = s;
    } else if (tid < 2 * D) {
        const int m = tid - D;
        float s = 0.f;
        for (int k = 0; k < D; k++) s += sWb[m * D + k] * sb1[k];
        suo[m] = s;
    }

    // P_r, P_o : 1024 outputs, one per thread
    {
        const int r = tid >> 6, m = tid & 63;
        float pr = 0.f, po = 0.f;
        for (int j = 0; j < D; j++) {
            const float w = sWl[r * D + j];
            pr += w * sWa[j * D + m];
            po += w * sWb[j * D + m];
        }
        sPr[tid] = pr;
        sPo[tid] = po;
    }
    __syncthreads();

    if (tid < NCLS) {
        float s = 0.f;
        for (int m = 0; m < D; m++) s += sWl[tid * D + m] * sur[m];
        g_v[tid] = s;
    } else if (tid < 2 * NCLS) {
        const int r = tid - NCLS;
        float s = 0.f;
        for (int m = 0; m < D; m++) s += sWl[r * D + m] * (suo[m] + sb2[m]);
        g_v[NCLS + r] = s + bl[r];
    }

    // ---- Phase 2 loads: W1r -> sWa, W1o -> sWb ----
    {
        const int nf4 = D * D / 4;
        for (int i = tid; i < nf4; i += 1024) {
            ((float4*)sWa)[i] = ((const float4*)W1r)[i];
            ((float4*)sWb)[i] = ((const float4*)W1o)[i];
        }
    }
    __syncthreads();

    // M1/M2/M3 : 3072 outputs, 3 per thread
    for (int idx = tid; idx < 3 * NCLS * D; idx += 1024) {
        const int which = idx / (NCLS * D);
        const int rem = idx - which * (NCLS * D);
        const int r = rem >> 6, k = rem & 63;
        float s = 0.f;
        if (which == 0) {
            for (int m = 0; m < D; m++) s += sPr[r * D + m] * sWa[m * D + k];
        } else if (which == 1) {
            for (int m = 0; m < D; m++)
                s += sPr[r * D + m] * sWb[m * D + k] + sPo[r * D + m] * sWa[m * D + k];
        } else {
            for (int m = 0; m < D; m++) s += sPo[r * D + m] * sWb[m * D + k];
        }
        ((float*)g_M4)[idx] = s;
    }
}

// ---------------------------------------------------------------------------
// transform: t1 = M1 x ; t2 = M2 x + v1 ; out = M3 x + c ; edge packing.
// 4 nodes per thread (64/block): M smem reads amortized 4x -> FMA-bound.
// ---------------------------------------------------------------------------
__global__ __launch_bounds__(256) void transform_kernel(
        const float* __restrict__ x, const void* __restrict__ eidx,
        float* __restrict__ d_out) {
    __shared__ float4 sM4[3 * NCLS * 16];  // 768 float4 = 12 KB (swizzled)
    __shared__ float4 sx4[64 * 16];        // 1024 float4 = 16 KB
    __shared__ float sv[2 * NCLS];
    const int tid = threadIdx.x;

    // Edge pack: 4 edges/thread, coalesced, guarded (782*1024 = 800768)
    {
        const int ebase = blockIdx.x * 1024 + tid;
        #pragma unroll
        for (int k = 0; k < 4; k++) {
            const int e = ebase + k * 256;
            if (e < NEDGES) {
                int es, ed;
                if (g_is64) {
                    const long long* ei = (const long long*)eidx;
                    es = (int)ei[e];
                    ed = (int)ei[NEDGES + e];
                } else {
                    const int* ei = (const int*)eidx;
                    es = ei[e];
                    ed = ei[NEDGES + e];
                }
                g_edge2[e] = make_int2(es, ed);
            }
        }
    }

    if (tid < 2 * NCLS) sv[tid] = g_v[tid];
    for (int i = tid; i < 3 * NCLS * 16; i += 256) {
        const int row = i >> 4, k4 = i & 15;
        sM4[(row << 4) | (k4 ^ (row & 15))] = g_M4[i];
    }
    // x tile: 64 nodes x 16 float4 = 1024 f4; 4 per thread; guard global range
    {
        const int gbase = blockIdx.x * 1024;
        #pragma unroll
        for (int k = 0; k < 4; k++) {
            const int i = tid + k * 256;
            const int gi = gbase + i;
            sx4[i] = (gi < NNODES * 16) ? ((const float4*)x)[gi]
                                        : make_float4(0.f, 0.f, 0.f, 0.f);
        }
    }
    __syncthreads();

    const int slot = tid >> 4;   // 0..15 -> 4 nodes each
    const int r = tid & 15;      // class
    float a1[4] = {0.f, 0.f, 0.f, 0.f};
    float a2[4] = {0.f, 0.f, 0.f, 0.f};
    float a3[4] = {0.f, 0.f, 0.f, 0.f};
    #pragma unroll 4
    for (int k4 = 0; k4 < 16; k4++) {
        const int sw = (r << 4) | (k4 ^ r);
        const float4 a = sM4[sw];
        const float4 b = sM4[256 + sw];
        const float4 c = sM4[512 + sw];
        #pragma unroll
        for (int q = 0; q < 4; q++) {
            const float4 xv = sx4[(slot * 4 + q) * 16 + k4];
            a1[q] += a.x * xv.x + a.y * xv.y + a.z * xv.z + a.w * xv.w;
            a2[q] += b.x * xv.x + b.y * xv.y + b.z * xv.z + b.w * xv.w;
            a3[q] += c.x * xv.x + c.y * xv.y + c.z * xv.z + c.w * xv.w;
        }
    }
    const int nodeBase = blockIdx.x * 64 + slot * 4;
    #pragma unroll
    for (int q = 0; q < 4; q++) {
        const int n = nodeBase + q;
        if (n < NNODES) {
            const int idx = n * NCLS + r;
            ((float*)g_t1)[idx] = a1[q];
            ((float*)g_t2)[idx] = a2[q] + sv[r];          // u2 + v1
            d_out[idx] = a3[q] + sv[NCLS + r];            // u3 + c
        }
    }
}

// ---------------------------------------------------------------------------
// Scatter: persistent grid-stride, 4 lanes/edge, 2 edges per iteration
// (one int4 index load -> 2 gathers -> 2 REDs). One wave on 148 SMs.
//   PASS 0: g_t2[dst] += t1[src]      PASS 1: out[dst] += t2[src]
// ---------------------------------------------------------------------------
template <int PASS>
__global__ __launch_bounds__(256) void scatter_kernel(float* __restrict__ d_out) {
    const int t = blockIdx.x * 256 + threadIdx.x;
    const int c = t & 3;                            // float4 component
    const int stride = (SCBLOCKS * 256) >> 2;       // 75776 group-slots
    const float4* srcArr = (PASS == 0) ? g_t1 : g_t2;
    for (int g = t >> 2; g < NEDGES / 2; g += stride) {
        const int4 p = ((const int4*)g_edge2)[g];   // edges 2g, 2g+1
        const float4 v0 = srcArr[p.x * 4 + c];
        const float4 v1 = srcArr[p.z * 4 + c];
        if (PASS == 0) {
            atomicAdd(&g_t2[p.y * 4 + c], v0);
            atomicAdd(&g_t2[p.w * 4 + c], v1);
        } else {
            atomicAdd((float4*)(d_out + p.y * NCLS) + c, v0);
            atomicAdd((float4*)(d_out + p.w * NCLS) + c, v1);
        }
    }
}

// ---------------------------------------------------------------------------
extern "C" void kernel_launch(void* const* d_in, const int* in_sizes, int n_in,
                              void* d_out, int out_size) {
    const float* x   = (const float*)d_in[0];
    const void*  eix = d_in[1];
    const float* W1r = (const float*)d_in[2];
    const float* b1  = (const float*)d_in[3];
    const float* W1o = (const float*)d_in[4];
    const float* W2r = (const float*)d_in[5];
    const float* b2  = (const float*)d_in[6];
    const float* W2o = (const float*)d_in[7];
    const float* Wl  = (const float*)d_in[8];
    const float* bl  = (const float*)d_in[9];
    float* out = (float*)d_out;

    // dtype detect + weight fold (one block, 1024 threads)
    dwfold_kernel<<<1, 1024>>>((const unsigned int*)eix, W1r, b1, W1o, W2r, b2, W2o, Wl, bl);

    // t1 = M1 x ; t2 = M2 x + v1 ; out = M3 x + c ; pack edges (64 nodes/block)
    transform_kernel<<<782, 256>>>(x, eix, out);

    // t2 += A t1 ; out += A t2   (persistent single-wave scatters)
    scatter_kernel<0><<<SCBLOCKS, 256>>>(out);
    scatter_kernel<1><<<SCBLOCKS, 256>>>(out);
}

// round 16
// speedup vs baseline: 1.0694x; 1.0694x over previous
#include <cuda_runtime.h>
#include <cuda_bf16.h>

// Problem constants (fixed by the reference)
#define NNODES 50000
#define NEDGES 800000
#define D      64
#define NCLS   16

// Scratch (device globals)
__device__ float4 g_t1[NNODES * NCLS / 4];   // M1 x
__device__ float4 g_t2[NNODES * NCLS / 4];   // u2 + v1, then += A t1
__device__ float4 g_M4[3 * NCLS * D / 4];    // M1, M2, M3
__device__ float  g_v[2 * NCLS];             // v1, c
__device__ int    g_is64;                    // 1 if edge_index is int64
__device__ int2   g_edge2[NEDGES];           // packed (src, dst)

// ---------------------------------------------------------------------------
// Fused: dtype detect + unified weight fold. ONE block, 1024 threads.
// ---------------------------------------------------------------------------
__global__ __launch_bounds__(1024) void dwfold_kernel(
        const unsigned int* __restrict__ widx,
        const float* __restrict__ W1r, const float* __restrict__ b1,
        const float* __restrict__ W1o, const float* __restrict__ W2r,
        const float* __restrict__ b2,  const float* __restrict__ W2o,
        const float* __restrict__ Wl,  const float* __restrict__ bl) {
    __shared__ float sWa[D * D];        // W2r then W1r
    __shared__ float sWb[D * D];        // W2o then W1o
    __shared__ float sWl[NCLS * D];
    __shared__ float sPr[NCLS * D];
    __shared__ float sPo[NCLS * D];
    __shared__ float sb1[D], sb2[D], sur[D], suo[D];
    __shared__ int any_nonzero;
    const int tid = threadIdx.x;

    // ---- dtype detect ----
    if (tid == 0) any_nonzero = 0;
    __syncthreads();
    {
        unsigned int acc = 0;
        for (int i = tid; i < 4096; i += 1024) acc |= widx[2 * i + 1];
        if (acc) any_nonzero = 1;
    }

    // ---- Phase 1 loads ----
    {
        const int nf4 = D * D / 4;                      // 1024
        for (int i = tid; i < nf4; i += 1024) {
            ((float4*)sWa)[i] = ((const float4*)W2r)[i];
            ((float4*)sWb)[i] = ((const float4*)W2o)[i];
        }
        if (tid < NCLS * D / 4)
            ((float4*)sWl)[tid] = ((const float4*)Wl)[tid];
        if (tid < D / 4) {
            ((float4*)sb1)[tid] = ((const float4*)b1)[tid];
            ((float4*)sb2)[tid] = ((const float4*)b2)[tid];
        }
    }
    __syncthreads();
    if (tid == 0) g_is64 = any_nonzero ? 0 : 1;

    if (tid < D) {
        float s = 0.f;
        for (int k = 0; k < D; k++) s += sWa[tid * D + k] * sb1[k];
        sur[tid] = s;
    } else if (tid < 2 * D) {
        const int m = tid - D;
        float s = 0.f;
        for (int k = 0; k < D; k++) s += sWb[m * D + k] * sb1[k];
        suo[m] = s;
    }

    // P_r, P_o : 1024 outputs, one per thread
    {
        const int r = tid >> 6, m = tid & 63;
        float pr = 0.f, po = 0.f;
        for (int j = 0; j < D; j++) {
            const float w = sWl[r * D + j];
            pr += w * sWa[j * D + m];
            po += w * sWb[j * D + m];
        }
        sPr[tid] = pr;
        sPo[tid] = po;
    }
    __syncthreads();

    if (tid < NCLS) {
        float s = 0.f;
        for (int m = 0; m < D; m++) s += sWl[tid * D + m] * sur[m];
        g_v[tid] = s;
    } else if (tid < 2 * NCLS) {
        const int r = tid - NCLS;
        float s = 0.f;
        for (int m = 0; m < D; m++) s += sWl[r * D + m] * (suo[m] + sb2[m]);
        g_v[NCLS + r] = s + bl[r];
    }

    // ---- Phase 2 loads: W1r -> sWa, W1o -> sWb ----
    {
        const int nf4 = D * D / 4;
        for (int i = tid; i < nf4; i += 1024) {
            ((float4*)sWa)[i] = ((const float4*)W1r)[i];
            ((float4*)sWb)[i] = ((const float4*)W1o)[i];
        }
    }
    __syncthreads();

    // M1/M2/M3 : 3072 outputs, 3 per thread
    for (int idx = tid; idx < 3 * NCLS * D; idx += 1024) {
        const int which = idx / (NCLS * D);
        const int rem = idx - which * (NCLS * D);
        const int r = rem >> 6, k = rem & 63;
        float s = 0.f;
        if (which == 0) {
            for (int m = 0; m < D; m++) s += sPr[r * D + m] * sWa[m * D + k];
        } else if (which == 1) {
            for (int m = 0; m < D; m++)
                s += sPr[r * D + m] * sWb[m * D + k] + sPo[r * D + m] * sWa[m * D + k];
        } else {
            for (int m = 0; m < D; m++) s += sPo[r * D + m] * sWb[m * D + k];
        }
        ((float*)g_M4)[idx] = s;
    }
}

// ---------------------------------------------------------------------------
// transform: t1 = M1 x ; t2 = M2 x + v1 ; out = M3 x + c ; edge packing.
// 4 nodes per thread (64/block): M smem reads amortized 4x -> FMA-bound.
// ---------------------------------------------------------------------------
__global__ __launch_bounds__(256) void transform_kernel(
        const float* __restrict__ x, const void* __restrict__ eidx,
        float* __restrict__ d_out) {
    __shared__ float4 sM4[3 * NCLS * 16];  // 768 float4 = 12 KB (swizzled)
    __shared__ float4 sx4[64 * 16];        // 1024 float4 = 16 KB
    __shared__ float sv[2 * NCLS];
    const int tid = threadIdx.x;

    // Edge pack: 4 edges/thread, coalesced, guarded (782*1024 = 800768)
    {
        const int ebase = blockIdx.x * 1024 + tid;
        #pragma unroll
        for (int k = 0; k < 4; k++) {
            const int e = ebase + k * 256;
            if (e < NEDGES) {
                int es, ed;
                if (g_is64) {
                    const long long* ei = (const long long*)eidx;
                    es = (int)ei[e];
                    ed = (int)ei[NEDGES + e];
                } else {
                    const int* ei = (const int*)eidx;
                    es = ei[e];
                    ed = ei[NEDGES + e];
                }
                g_edge2[e] = make_int2(es, ed);
            }
        }
    }

    if (tid < 2 * NCLS) sv[tid] = g_v[tid];
    for (int i = tid; i < 3 * NCLS * 16; i += 256) {
        const int row = i >> 4, k4 = i & 15;
        sM4[(row << 4) | (k4 ^ (row & 15))] = g_M4[i];
    }
    // x tile: 64 nodes x 16 float4 = 1024 f4; 4 per thread; guard global range
    {
        const int gbase = blockIdx.x * 1024;
        #pragma unroll
        for (int k = 0; k < 4; k++) {
            const int i = tid + k * 256;
            const int gi = gbase + i;
            sx4[i] = (gi < NNODES * 16) ? ((const float4*)x)[gi]
                                        : make_float4(0.f, 0.f, 0.f, 0.f);
        }
    }
    __syncthreads();

    const int slot = tid >> 4;   // 0..15 -> 4 nodes each
    const int r = tid & 15;      // class
    float a1[4] = {0.f, 0.f, 0.f, 0.f};
    float a2[4] = {0.f, 0.f, 0.f, 0.f};
    float a3[4] = {0.f, 0.f, 0.f, 0.f};
    #pragma unroll 4
    for (int k4 = 0; k4 < 16; k4++) {
        const int sw = (r << 4) | (k4 ^ r);
        const float4 a = sM4[sw];
        const float4 b = sM4[256 + sw];
        const float4 c = sM4[512 + sw];
        #pragma unroll
        for (int q = 0; q < 4; q++) {
            const float4 xv = sx4[(slot * 4 + q) * 16 + k4];
            a1[q] += a.x * xv.x + a.y * xv.y + a.z * xv.z + a.w * xv.w;
            a2[q] += b.x * xv.x + b.y * xv.y + b.z * xv.z + b.w * xv.w;
            a3[q] += c.x * xv.x + c.y * xv.y + c.z * xv.z + c.w * xv.w;
        }
    }
    const int nodeBase = blockIdx.x * 64 + slot * 4;
    #pragma unroll
    for (int q = 0; q < 4; q++) {
        const int n = nodeBase + q;
        if (n < NNODES) {
            const int idx = n * NCLS + r;
            ((float*)g_t1)[idx] = a1[q];
            ((float*)g_t2)[idx] = a2[q] + sv[r];          // u2 + v1
            d_out[idx] = a3[q] + sv[NCLS + r];            // u3 + c
        }
    }
}

// ---------------------------------------------------------------------------
// Scatter: 4 lanes/edge, 4 edges/thread (adjacent pairs -> 2x LDG.128 index
// loads), fixed mapping (no loop -> 32 regs, high occupancy). 512-thread
// blocks to halve CTA count vs R14.
//   PASS 0: g_t2[dst] += t1[src]      PASS 1: out[dst] += t2[src]
// ---------------------------------------------------------------------------
template <int PASS>
__global__ __launch_bounds__(512) void scatter_kernel(float* __restrict__ d_out) {
    const int t = blockIdx.x * 512 + threadIdx.x;   // 1563*512 >= 800000
    const int g = t >> 2;                           // pair group
    const int c = t & 3;                            // float4 component
    if (g >= NEDGES / 4) return;                    // 200000 groups
    const int4 p0 = ((const int4*)g_edge2)[g];                    // edges 2g, 2g+1
    const int4 p1 = ((const int4*)g_edge2)[g + NEDGES / 4];       // + E/2
    const float4* srcArr = (PASS == 0) ? g_t1 : g_t2;
    const float4 v0 = srcArr[p0.x * 4 + c];
    const float4 v1 = srcArr[p0.z * 4 + c];
    const float4 v2 = srcArr[p1.x * 4 + c];
    const float4 v3 = srcArr[p1.z * 4 + c];
    if (PASS == 0) {
        atomicAdd(&g_t2[p0.y * 4 + c], v0);
        atomicAdd(&g_t2[p0.w * 4 + c], v1);
        atomicAdd(&g_t2[p1.y * 4 + c], v2);
        atomicAdd(&g_t2[p1.w * 4 + c], v3);
    } else {
        atomicAdd((float4*)(d_out + p0.y * NCLS) + c, v0);
        atomicAdd((float4*)(d_out + p0.w * NCLS) + c, v1);
        atomicAdd((float4*)(d_out + p1.y * NCLS) + c, v2);
        atomicAdd((float4*)(d_out + p1.w * NCLS) + c, v3);
    }
}

// ---------------------------------------------------------------------------
extern "C" void kernel_launch(void* const* d_in, const int* in_sizes, int n_in,
                              void* d_out, int out_size) {
    const float* x   = (const float*)d_in[0];
    const void*  eix = d_in[1];
    const float* W1r = (const float*)d_in[2];
    const float* b1  = (const float*)d_in[3];
    const float* W1o = (const float*)d_in[4];
    const float* W2r = (const float*)d_in[5];
    const float* b2  = (const float*)d_in[6];
    const float* W2o = (const float*)d_in[7];
    const float* Wl  = (const float*)d_in[8];
    const float* bl  = (const float*)d_in[9];
    float* out = (float*)d_out;

    // dtype detect + weight fold (one block, 1024 threads)
    dwfold_kernel<<<1, 1024>>>((const unsigned int*)eix, W1r, b1, W1o, W2r, b2, W2o, Wl, bl);

    // t1 = M1 x ; t2 = M2 x + v1 ; out = M3 x + c ; pack edges (64 nodes/block)
    transform_kernel<<<782, 256>>>(x, eix, out);

    // t2 += A t1 ; out += A t2   (4 lanes/edge, 4 edges/thread, 512-thr blocks)
    const int scBlocks = (NEDGES + 2047) / 2048 + ((NEDGES % 2048) ? 0 : 0); // 391*... compute exact
    const int blocks = (NEDGES / 4 * 4 + 511) / 512;   // 200000 groups *4 lanes /512 = 1563
    (void)scBlocks;
    scatter_kernel<0><<<blocks, 512>>>(out);
    scatter_kernel<1><<<blocks, 512>>>(out);
}

// round 17
// speedup vs baseline: 1.0717x; 1.0022x over previous
#include <cuda_runtime.h>
#include <cuda_bf16.h>

// Problem constants (fixed by the reference)
#define NNODES 50000
#define NEDGES 800000
#define D      64
#define NCLS   16

// Scratch (device globals)
__device__ float4 g_t1[NNODES * NCLS / 4];   // M1 x
__device__ float4 g_t2[NNODES * NCLS / 4];   // u2 + v1, then += A t1
__device__ float4 g_M4[3 * NCLS * D / 4];    // M1, M2, M3
__device__ float  g_v[2 * NCLS];             // v1, c
__device__ int    g_is64;                    // 1 if edge_index is int64
__device__ int2   g_edge2[NEDGES];           // packed (src, dst)

// ---------------------------------------------------------------------------
// Fused: dtype detect + unified weight fold. ONE block, 1024 threads.
//   Phase 1: P_r = Wl*W2r, P_o = Wl*W2o; v1 = Wl*(W2r b1); c = Wl*(W2o b1+b2)+bl
//   Phase 2: M1 = P_r*W1r, M2 = P_r*W1o + P_o*W1r, M3 = P_o*W1o
// ---------------------------------------------------------------------------
__global__ __launch_bounds__(1024) void dwfold_kernel(
        const unsigned int* __restrict__ widx,
        const float* __restrict__ W1r, const float* __restrict__ b1,
        const float* __restrict__ W1o, const float* __restrict__ W2r,
        const float* __restrict__ b2,  const float* __restrict__ W2o,
        const float* __restrict__ Wl,  const float* __restrict__ bl) {
    __shared__ float sWa[D * D];        // W2r then W1r
    __shared__ float sWb[D * D];        // W2o then W1o
    __shared__ float sWl[NCLS * D];
    __shared__ float sPr[NCLS * D];
    __shared__ float sPo[NCLS * D];
    __shared__ float sb1[D], sb2[D], sur[D], suo[D];
    __shared__ int any_nonzero;
    const int tid = threadIdx.x;

    // ---- dtype detect: int64 indices in [0,50000) have all-zero hi words ----
    if (tid == 0) any_nonzero = 0;
    __syncthreads();
    {
        unsigned int acc = 0;
        for (int i = tid; i < 4096; i += 1024) acc |= widx[2 * i + 1];
        if (acc) any_nonzero = 1;
    }

    // ---- Phase 1 loads ----
    {
        const int nf4 = D * D / 4;                      // 1024
        for (int i = tid; i < nf4; i += 1024) {
            ((float4*)sWa)[i] = ((const float4*)W2r)[i];
            ((float4*)sWb)[i] = ((const float4*)W2o)[i];
        }
        if (tid < NCLS * D / 4)
            ((float4*)sWl)[tid] = ((const float4*)Wl)[tid];
        if (tid < D / 4) {
            ((float4*)sb1)[tid] = ((const float4*)b1)[tid];
            ((float4*)sb2)[tid] = ((const float4*)b2)[tid];
        }
    }
    __syncthreads();
    if (tid == 0) g_is64 = any_nonzero ? 0 : 1;

    if (tid < D) {
        float s = 0.f;
        for (int k = 0; k < D; k++) s += sWa[tid * D + k] * sb1[k];
        sur[tid] = s;
    } else if (tid < 2 * D) {
        const int m = tid - D;
        float s = 0.f;
        for (int k = 0; k < D; k++) s += sWb[m * D + k] * sb1[k];
        suo[m] = s;
    }

    // P_r, P_o : 1024 outputs, one per thread
    {
        const int r = tid >> 6, m = tid & 63;
        float pr = 0.f, po = 0.f;
        for (int j = 0; j < D; j++) {
            const float w = sWl[r * D + j];
            pr += w * sWa[j * D + m];
            po += w * sWb[j * D + m];
        }
        sPr[tid] = pr;
        sPo[tid] = po;
    }
    __syncthreads();

    if (tid < NCLS) {
        float s = 0.f;
        for (int m = 0; m < D; m++) s += sWl[tid * D + m] * sur[m];
        g_v[tid] = s;
    } else if (tid < 2 * NCLS) {
        const int r = tid - NCLS;
        float s = 0.f;
        for (int m = 0; m < D; m++) s += sWl[r * D + m] * (suo[m] + sb2[m]);
        g_v[NCLS + r] = s + bl[r];
    }

    // ---- Phase 2 loads: W1r -> sWa, W1o -> sWb ----
    {
        const int nf4 = D * D / 4;
        for (int i = tid; i < nf4; i += 1024) {
            ((float4*)sWa)[i] = ((const float4*)W1r)[i];
            ((float4*)sWb)[i] = ((const float4*)W1o)[i];
        }
    }
    __syncthreads();

    // M1/M2/M3 : 3072 outputs, 3 per thread
    for (int idx = tid; idx < 3 * NCLS * D; idx += 1024) {
        const int which = idx / (NCLS * D);
        const int rem = idx - which * (NCLS * D);
        const int r = rem >> 6, k = rem & 63;
        float s = 0.f;
        if (which == 0) {
            for (int m = 0; m < D; m++) s += sPr[r * D + m] * sWa[m * D + k];
        } else if (which == 1) {
            for (int m = 0; m < D; m++)
                s += sPr[r * D + m] * sWb[m * D + k] + sPo[r * D + m] * sWa[m * D + k];
        } else {
            for (int m = 0; m < D; m++) s += sPo[r * D + m] * sWb[m * D + k];
        }
        ((float*)g_M4)[idx] = s;
    }
}

// ---------------------------------------------------------------------------
// transform: t1 = M1 x ; t2 = M2 x + v1 ; out = M3 x + c ; edge packing.
// 4 nodes per thread (64/block): M smem reads amortized 4x -> FMA-bound.
// LDS.128 with XOR-swizzled M tile. Grid 782 (last block partial, guarded).
// ---------------------------------------------------------------------------
__global__ __launch_bounds__(256) void transform_kernel(
        const float* __restrict__ x, const void* __restrict__ eidx,
        float* __restrict__ d_out) {
    __shared__ float4 sM4[3 * NCLS * 16];  // 768 float4 = 12 KB (swizzled)
    __shared__ float4 sx4[64 * 16];        // 1024 float4 = 16 KB
    __shared__ float sv[2 * NCLS];
    const int tid = threadIdx.x;

    // Edge pack: 4 edges/thread, coalesced, guarded (782*1024 = 800768)
    {
        const int ebase = blockIdx.x * 1024 + tid;
        #pragma unroll
        for (int k = 0; k < 4; k++) {
            const int e = ebase + k * 256;
            if (e < NEDGES) {
                int es, ed;
                if (g_is64) {
                    const long long* ei = (const long long*)eidx;
                    es = (int)ei[e];
                    ed = (int)ei[NEDGES + e];
                } else {
                    const int* ei = (const int*)eidx;
                    es = ei[e];
                    ed = ei[NEDGES + e];
                }
                g_edge2[e] = make_int2(es, ed);
            }
        }
    }

    if (tid < 2 * NCLS) sv[tid] = g_v[tid];
    for (int i = tid; i < 3 * NCLS * 16; i += 256) {
        const int row = i >> 4, k4 = i & 15;
        sM4[(row << 4) | (k4 ^ (row & 15))] = g_M4[i];
    }
    // x tile: 64 nodes x 16 float4 = 1024 f4; 4 per thread; guard global range
    {
        const int gbase = blockIdx.x * 1024;
        #pragma unroll
        for (int k = 0; k < 4; k++) {
            const int i = tid + k * 256;
            const int gi = gbase + i;
            sx4[i] = (gi < NNODES * 16) ? ((const float4*)x)[gi]
                                        : make_float4(0.f, 0.f, 0.f, 0.f);
        }
    }
    __syncthreads();

    const int slot = tid >> 4;   // 0..15 -> 4 nodes each
    const int r = tid & 15;      // class
    float a1[4] = {0.f, 0.f, 0.f, 0.f};
    float a2[4] = {0.f, 0.f, 0.f, 0.f};
    float a3[4] = {0.f, 0.f, 0.f, 0.f};
    #pragma unroll 4
    for (int k4 = 0; k4 < 16; k4++) {
        const int sw = (r << 4) | (k4 ^ r);
        const float4 a = sM4[sw];
        const float4 b = sM4[256 + sw];
        const float4 c = sM4[512 + sw];
        #pragma unroll
        for (int q = 0; q < 4; q++) {
            const float4 xv = sx4[(slot * 4 + q) * 16 + k4];
            a1[q] += a.x * xv.x + a.y * xv.y + a.z * xv.z + a.w * xv.w;
            a2[q] += b.x * xv.x + b.y * xv.y + b.z * xv.z + b.w * xv.w;
            a3[q] += c.x * xv.x + c.y * xv.y + c.z * xv.z + c.w * xv.w;
        }
    }
    const int nodeBase = blockIdx.x * 64 + slot * 4;
    #pragma unroll
    for (int q = 0; q < 4; q++) {
        const int n = nodeBase + q;
        if (n < NNODES) {
            const int idx = n * NCLS + r;
            ((float*)g_t1)[idx] = a1[q];
            ((float*)g_t2)[idx] = a2[q] + sv[r];          // u2 + v1
            d_out[idx] = a3[q] + sv[NCLS + r];            // u3 + c
        }
    }
}

// ---------------------------------------------------------------------------
// Scatter (converged config = R14): 4 lanes/edge, 4 edges/thread grouped in
// adjacent pairs (2x LDG.128 index loads), fixed mapping, 256-thr blocks,
// exact grid (3125*256 = 800000 lane-slots), 32 regs -> ~80% occupancy.
//   PASS 0: g_t2[dst] += t1[src]      PASS 1: out[dst] += t2[src]
// ---------------------------------------------------------------------------
template <int PASS>
__global__ __launch_bounds__(256) void scatter_kernel(float* __restrict__ d_out) {
    const int t = blockIdx.x * 256 + threadIdx.x;   // 3125*256 = 800000 exact
    const int g = t >> 2;                           // pair group in [0, 200000)
    const int c = t & 3;                            // float4 component
    const int4 p0 = ((const int4*)g_edge2)[g];                    // edges 2g, 2g+1
    const int4 p1 = ((const int4*)g_edge2)[g + NEDGES / 4];       // + E/2
    const float4* srcArr = (PASS == 0) ? g_t1 : g_t2;
    const float4 v0 = srcArr[p0.x * 4 + c];
    const float4 v1 = srcArr[p0.z * 4 + c];
    const float4 v2 = srcArr[p1.x * 4 + c];
    const float4 v3 = srcArr[p1.z * 4 + c];
    if (PASS == 0) {
        atomicAdd(&g_t2[p0.y * 4 + c], v0);
        atomicAdd(&g_t2[p0.w * 4 + c], v1);
        atomicAdd(&g_t2[p1.y * 4 + c], v2);
        atomicAdd(&g_t2[p1.w * 4 + c], v3);
    } else {
        atomicAdd((float4*)(d_out + p0.y * NCLS) + c, v0);
        atomicAdd((float4*)(d_out + p0.w * NCLS) + c, v1);
        atomicAdd((float4*)(d_out + p1.y * NCLS) + c, v2);
        atomicAdd((float4*)(d_out + p1.w * NCLS) + c, v3);
    }
}

// ---------------------------------------------------------------------------
extern "C" void kernel_launch(void* const* d_in, const int* in_sizes, int n_in,
                              void* d_out, int out_size) {
    const float* x   = (const float*)d_in[0];
    const void*  eix = d_in[1];
    const float* W1r = (const float*)d_in[2];
    const float* b1  = (const float*)d_in[3];
    const float* W1o = (const float*)d_in[4];
    const float* W2r = (const float*)d_in[5];
    const float* b2  = (const float*)d_in[6];
    const float* W2o = (const float*)d_in[7];
    const float* Wl  = (const float*)d_in[8];
    const float* bl  = (const float*)d_in[9];
    float* out = (float*)d_out;

    // dtype detect + weight fold (one block, 1024 threads)
    dwfold_kernel<<<1, 1024>>>((const unsigned int*)eix, W1r, b1, W1o, W2r, b2, W2o, Wl, bl);

    // t1 = M1 x ; t2 = M2 x + v1 ; out = M3 x + c ; pack edges (64 nodes/block)
    transform_kernel<<<782, 256>>>(x, eix, out);

    // t2 += A t1 ; out += A t2   (4 lanes/edge, 4 edges/thread)
    scatter_kernel<0><<<3125, 256>>>(out);
    scatter_kernel<1><<<3125, 256>>>(out);
}